// round 13
// baseline (speedup 1.0000x reference)
#include <cuda_runtime.h>
#include <cuda_bf16.h>
#include <cstddef>
#include <cstdint>

#define Bq   128
#define Tq   64
#define Hq   512
#define Vq   10000
#define Gq   2048            // 4*H
#define BTq  (Bq*Tq)         // 8192
#define NBLK 79              // ceil(V/128)

// ---------------- scratch ----------------
__device__ float g_xw0[(size_t)BTq * Gq];      // row-major [bt][gatecol]
__device__ float g_out[(size_t)BTq * Hq];
__device__ float g_pm[(size_t)BTq * NBLK];
__device__ float g_ps[(size_t)BTq * NBLK];
__device__ float g_zl[BTq];
__device__ float g_xent[BTq];
__device__ float g_h0[2][Bq * Hq];
__device__ float g_h1[2][Bq * Hq];
__device__ float g_c0[Bq * Hq];
__device__ float g_c1[Bq * Hq];
__device__ float g_o0[2][Bq * Hq];             // dbl-buffered by t parity

__device__ __forceinline__ float sigf(float x) { return 1.f / (1.f + expf(-x)); }

__device__ __forceinline__ uint32_t s2u(const void* p) {
    return (uint32_t)__cvta_generic_to_shared(p);
}
__device__ __forceinline__ void cpa16(uint32_t dst, const void* src) {
    asm volatile("cp.async.cg.shared.global [%0], [%1], 16;" :: "r"(dst), "l"(src));
}
__device__ __forceinline__ void cpa16p(uint32_t dst, const void* src, bool pred) {
    int sz = pred ? 16 : 0;
    asm volatile("cp.async.cg.shared.global [%0], [%1], 16, %2;" :: "r"(dst), "l"(src), "r"(sz));
}
#define CP_COMMIT asm volatile("cp.async.commit_group;")
#define CP_WAIT1  asm volatile("cp.async.wait_group 1;")
#define CP_WAIT2  asm volatile("cp.async.wait_group 2;")

__device__ __forceinline__ void mma_tf32(float& d0, float& d1, float& d2, float& d3,
                                         unsigned a0, unsigned a1, unsigned a2, unsigned a3,
                                         unsigned b0, unsigned b1) {
    asm volatile(
        "mma.sync.aligned.m16n8k8.row.col.f32.tf32.tf32.f32 "
        "{%0,%1,%2,%3}, {%4,%5,%6,%7}, {%8,%9}, {%0,%1,%2,%3};"
        : "+f"(d0), "+f"(d1), "+f"(d2), "+f"(d3)
        : "r"(a0), "r"(a1), "r"(a2), "r"(a3), "r"(b0), "r"(b1));
}

// ---------------- init ----------------
__global__ void k_init() {
    int i = blockIdx.x * blockDim.x + threadIdx.x;
    if (i < Bq * Hq) {
        g_h0[0][i] = 0.f; g_c0[i] = 0.f;
        g_h1[0][i] = 0.f; g_c1[i] = 0.f;
    }
}

// =======================================================================
// big tf32 GEMMs (R10 proven): block 128x128, warp 32x64, k-chunk 16
// =======================================================================
#define ASTR 20
#define BSTR 136

__global__ void k_xw0_tf32(const float* __restrict__ emb, const int* __restrict__ feat,
                           const float* __restrict__ Bm, const float* __restrict__ bias) {
    const int N = Gq, K = Hq;
    __shared__ float As[2][128 * ASTR];
    __shared__ float Bs[2][16 * BSTR];
    const int tid = threadIdx.x;
    const int bx = blockIdx.x, by = blockIdx.y;
    const int warp = tid >> 5, lane = tid & 31;
    const int wm = warp & 3, wn = warp >> 2;
    const int gID = lane >> 2, tig = lane & 3;

    const int arow = tid >> 2;
    const int aq   = (tid & 3) * 4;
    const float* asrc0 = emb + (size_t)feat[by * 128 + arow] * K + aq;
    const float* asrc1 = emb + (size_t)feat[by * 128 + arow + 64] * K + aq;
    const int bk = tid >> 5, bq = tid & 31;
    const float* bsrc = Bm + (size_t)bk * N + bx * 128 + bq * 4;

    float acc[2][8][4];
#pragma unroll
    for (int mt = 0; mt < 2; ++mt)
#pragma unroll
        for (int nt = 0; nt < 8; ++nt)
#pragma unroll
            for (int e = 0; e < 4; ++e) acc[mt][nt][e] = 0.f;

    const int NC = K / 16;
    {
        cpa16(s2u(&As[0][arow * ASTR + aq]), asrc0);
        cpa16(s2u(&As[0][(arow + 64) * ASTR + aq]), asrc1);
        cpa16(s2u(&Bs[0][bk * BSTR + bq * 4]), bsrc);
        cpa16(s2u(&Bs[0][(bk + 8) * BSTR + bq * 4]), bsrc + (size_t)8 * N);
    }
    CP_COMMIT;
    for (int c = 0; c < NC; ++c) {
        const int cur = c & 1, nxt = cur ^ 1;
        if (c + 1 < NC) {
            int k0 = (c + 1) * 16;
            cpa16(s2u(&As[nxt][arow * ASTR + aq]), asrc0 + k0);
            cpa16(s2u(&As[nxt][(arow + 64) * ASTR + aq]), asrc1 + k0);
            cpa16(s2u(&Bs[nxt][bk * BSTR + bq * 4]), bsrc + (size_t)k0 * N);
            cpa16(s2u(&Bs[nxt][(bk + 8) * BSTR + bq * 4]), bsrc + (size_t)(k0 + 8) * N);
        }
        CP_COMMIT;
        CP_WAIT1;
        __syncthreads();
        const unsigned* Au = (const unsigned*)As[cur];
        const unsigned* Bu = (const unsigned*)Bs[cur];
#pragma unroll
        for (int ks = 0; ks < 2; ++ks) {
            unsigned a[2][4];
#pragma unroll
            for (int mt = 0; mt < 2; ++mt) {
                int mr = wm * 32 + mt * 16;
                a[mt][0] = Au[(mr + gID    ) * ASTR + ks * 8 + tig];
                a[mt][1] = Au[(mr + gID + 8) * ASTR + ks * 8 + tig];
                a[mt][2] = Au[(mr + gID    ) * ASTR + ks * 8 + tig + 4];
                a[mt][3] = Au[(mr + gID + 8) * ASTR + ks * 8 + tig + 4];
            }
#pragma unroll
            for (int nt = 0; nt < 8; ++nt) {
                int nc = wn * 64 + nt * 8 + gID;
                unsigned b0 = Bu[(ks * 8 + tig    ) * BSTR + nc];
                unsigned b1 = Bu[(ks * 8 + tig + 4) * BSTR + nc];
#pragma unroll
                for (int mt = 0; mt < 2; ++mt)
                    mma_tf32(acc[mt][nt][0], acc[mt][nt][1], acc[mt][nt][2], acc[mt][nt][3],
                             a[mt][0], a[mt][1], a[mt][2], a[mt][3], b0, b1);
            }
        }
        __syncthreads();
    }
#pragma unroll
    for (int mt = 0; mt < 2; ++mt) {
#pragma unroll
        for (int er = 0; er < 2; ++er) {
            int gm = by * 128 + wm * 32 + mt * 16 + gID + er * 8;
            float* crow = g_xw0 + (size_t)gm * N;
#pragma unroll
            for (int nt = 0; nt < 8; ++nt) {
                int gn = bx * 128 + wn * 64 + nt * 8 + tig * 2;
                float2 v = {acc[mt][nt][er * 2 + 0] + bias[gn],
                            acc[mt][nt][er * 2 + 1] + bias[gn + 1]};
                *(float2*)(crow + gn) = v;
            }
        }
    }
}

__global__ void k_logits_tf32(const float* __restrict__ Bm,
                              const float* __restrict__ bias,
                              const int* __restrict__ labels) {
    const int N = Vq, K = Hq;
    __shared__ float As[2][128 * ASTR];
    __shared__ float Bs[2][16 * BSTR];
    __shared__ float pm[128][9];
    __shared__ float ps[128][9];
    const int tid = threadIdx.x;
    const int bx = blockIdx.x, by = blockIdx.y;
    const int warp = tid >> 5, lane = tid & 31;
    const int wm = warp & 3, wn = warp >> 2;
    const int gID = lane >> 2, tig = lane & 3;

    const int arow = tid >> 2;
    const int aq   = (tid & 3) * 4;
    const float* asrc0 = g_out + (size_t)(by * 128 + arow) * K + aq;
    const float* asrc1 = asrc0 + (size_t)64 * K;
    const int bk = tid >> 5, bq = tid & 31;
    const int gnq = bx * 128 + bq * 4;
    const bool bpred = (gnq + 3 < N);
    const float* bsrc = Bm + (size_t)bk * N + (bpred ? gnq : 0);

    float acc[2][8][4];
#pragma unroll
    for (int mt = 0; mt < 2; ++mt)
#pragma unroll
        for (int nt = 0; nt < 8; ++nt)
#pragma unroll
            for (int e = 0; e < 4; ++e) acc[mt][nt][e] = 0.f;

    const int NC = K / 16;
    {
        cpa16(s2u(&As[0][arow * ASTR + aq]), asrc0);
        cpa16(s2u(&As[0][(arow + 64) * ASTR + aq]), asrc1);
        cpa16p(s2u(&Bs[0][bk * BSTR + bq * 4]), bsrc, bpred);
        cpa16p(s2u(&Bs[0][(bk + 8) * BSTR + bq * 4]), bsrc + (size_t)8 * N, bpred);
    }
    CP_COMMIT;
    for (int c = 0; c < NC; ++c) {
        const int cur = c & 1, nxt = cur ^ 1;
        if (c + 1 < NC) {
            int k0 = (c + 1) * 16;
            cpa16(s2u(&As[nxt][arow * ASTR + aq]), asrc0 + k0);
            cpa16(s2u(&As[nxt][(arow + 64) * ASTR + aq]), asrc1 + k0);
            cpa16p(s2u(&Bs[nxt][bk * BSTR + bq * 4]), bsrc + (size_t)k0 * N, bpred);
            cpa16p(s2u(&Bs[nxt][(bk + 8) * BSTR + bq * 4]), bsrc + (size_t)(k0 + 8) * N, bpred);
        }
        CP_COMMIT;
        CP_WAIT1;
        __syncthreads();
        const unsigned* Au = (const unsigned*)As[cur];
        const unsigned* Bu = (const unsigned*)Bs[cur];
#pragma unroll
        for (int ks = 0; ks < 2; ++ks) {
            unsigned a[2][4];
#pragma unroll
            for (int mt = 0; mt < 2; ++mt) {
                int mr = wm * 32 + mt * 16;
                a[mt][0] = Au[(mr + gID    ) * ASTR + ks * 8 + tig];
                a[mt][1] = Au[(mr + gID + 8) * ASTR + ks * 8 + tig];
                a[mt][2] = Au[(mr + gID    ) * ASTR + ks * 8 + tig + 4];
                a[mt][3] = Au[(mr + gID + 8) * ASTR + ks * 8 + tig + 4];
            }
#pragma unroll
            for (int nt = 0; nt < 8; ++nt) {
                int nc = wn * 64 + nt * 8 + gID;
                unsigned b0 = Bu[(ks * 8 + tig    ) * BSTR + nc];
                unsigned b1 = Bu[(ks * 8 + tig + 4) * BSTR + nc];
#pragma unroll
                for (int mt = 0; mt < 2; ++mt)
                    mma_tf32(acc[mt][nt][0], acc[mt][nt][1], acc[mt][nt][2], acc[mt][nt][3],
                             a[mt][0], a[mt][1], a[mt][2], a[mt][3], b0, b1);
            }
        }
        __syncthreads();
    }

#pragma unroll
    for (int mt = 0; mt < 2; ++mt) {
#pragma unroll
        for (int er = 0; er < 2; ++er) {
            int lr = wm * 32 + mt * 16 + gID + er * 8;
            int gm = by * 128 + lr;
            int lab = labels[gm];
            float lm = -1e30f, lsum = 0.f;
            float v[16];
#pragma unroll
            for (int nt = 0; nt < 8; ++nt) {
#pragma unroll
                for (int e = 0; e < 2; ++e) {
                    int gn = bx * 128 + wn * 64 + nt * 8 + tig * 2 + e;
                    float cc = acc[mt][nt][er * 2 + e];
                    if (gn < N) {
                        float z = cc + bias[gn];
                        v[nt * 2 + e] = z;
                        if (gn == lab) g_zl[gm] = z;
                        lm = fmaxf(lm, z);
                    } else v[nt * 2 + e] = -1e30f;
                }
            }
#pragma unroll
            for (int q = 0; q < 16; ++q) lsum += expf(v[q] - lm);
            if (lm <= -1e30f) lsum = 0.f;
            pm[lr][wn * 4 + tig] = lm;
            ps[lr][wn * 4 + tig] = lsum;
        }
    }
    __syncthreads();
    if (tid < 128) {
        float m = -1e30f, s = 0.f;
#pragma unroll
        for (int x = 0; x < 8; ++x) {
            float m2 = pm[tid][x], s2 = ps[tid][x];
            float M = fmaxf(m, m2);
            s = s * expf(m - M) + s2 * expf(m2 - M);
            m = M;
        }
        int gm = by * 128 + tid;
        g_pm[(size_t)gm * NBLK + bx] = m;
        g_ps[(size_t)gm * NBLK + bx] = s;
    }
}

// =======================================================================
// LSTM steps: WARP-PRIVATE barrier-free cp.async pipelines.
// Block = 128 rows x 16 gate-cols (j0 = bx*4); warp wm owns rows wm*16..+15
// and its own copy of the 16x16 B tile.  4-stage ring per warp, wait_group 2,
// __syncwarp only.  Dyn SMEM: 8 warps x 4 stages x (16*SA + 16*SB) floats.
// =======================================================================
#define SA  20
#define SB  24
#define STGF (16 * SA + 16 * SB)                  // 704 floats per stage
#define STEP_SMEM (8 * 4 * STGF * 4)              // 90112 bytes

__device__ __forceinline__ void warp_mma_loop(
        const float* __restrict__ A0, const float* __restrict__ A1,
        const float* __restrict__ W0, const float* __restrict__ W1,
        int nphase, int j0, float* wbase,
        int wm, int lane, int gID, int tig, float acc[2][4]) {
    const int NC = nphase * 32;
    const int arl = lane >> 1, aq = (lane & 1) * 8;   // A: 2 lanes/row, 2 cp each
    const int br  = lane & 15, bg = lane >> 4;        // B: items lane, lane+32

    auto issue = [&](int cc) {
        const float* Ap = (cc < 32) ? A0 : A1;
        const float* Wp = (cc < 32) ? W0 : W1;
        int k0 = (cc & 31) * 16;
        float* Ab = wbase + (cc & 3) * STGF;
        float* Bb = Ab + 16 * SA;
        const float* as = Ap + (size_t)(wm * 16 + arl) * Hq + k0 + aq;
        cpa16(s2u(&Ab[arl * SA + aq]),     as);
        cpa16(s2u(&Ab[arl * SA + aq + 4]), as + 4);
        cpa16(s2u(&Bb[br * SB + bg * 4]),
              Wp + (size_t)(k0 + br) * Gq + bg * Hq + j0);
        cpa16(s2u(&Bb[br * SB + (bg + 2) * 4]),
              Wp + (size_t)(k0 + br) * Gq + (bg + 2) * Hq + j0);
    };

    issue(0); CP_COMMIT;
    issue(1); CP_COMMIT;
    issue(2); CP_COMMIT;
    for (int c = 0; c < NC; ++c) {
        CP_WAIT2;                  // per-lane: chunk c's group retired
        __syncwarp();              // all lanes' fills for chunk c visible
        const unsigned* Au = (const unsigned*)(wbase + (c & 3) * STGF);
        const unsigned* Bu = Au + 16 * SA;
#pragma unroll
        for (int ks = 0; ks < 2; ++ks) {
            unsigned a0 = Au[(gID    ) * SA + ks * 8 + tig];
            unsigned a1 = Au[(gID + 8) * SA + ks * 8 + tig];
            unsigned a2 = Au[(gID    ) * SA + ks * 8 + tig + 4];
            unsigned a3 = Au[(gID + 8) * SA + ks * 8 + tig + 4];
#pragma unroll
            for (int nt = 0; nt < 2; ++nt) {
                int n = nt * 8 + gID;
                unsigned b0 = Bu[(ks * 8 + tig    ) * SB + n];
                unsigned b1 = Bu[(ks * 8 + tig + 4) * SB + n];
                mma_tf32(acc[nt][0], acc[nt][1], acc[nt][2], acc[nt][3],
                         a0, a1, a2, a3, b0, b1);
            }
        }
        __syncwarp();              // all lanes done reading buf (c&3)
        if (c + 3 < NC) issue(c + 3);   // overwrites buf (c-1)&3: safe
        CP_COMMIT;                 // unconditional: group index == chunk index
    }
}

__device__ __forceinline__ void stage_accs(float* stg, int wm, int gID, int tig,
                                           float acc[2][4]) {
#pragma unroll
    for (int nt = 0; nt < 2; ++nt)
#pragma unroll
        for (int er = 0; er < 2; ++er)
#pragma unroll
            for (int e = 0; e < 2; ++e)
                stg[(wm * 16 + gID + er * 8) * 17 + nt * 8 + tig * 2 + e] =
                    acc[nt][er * 2 + e];
}

// ---- layer 0 body ----
__device__ void layer0_body(int t, int jblk, const int* __restrict__ seq_len,
                            const float* __restrict__ W0h, float* dynsm) {
    const int tid = threadIdx.x, lane = tid & 31, wm = tid >> 5;
    const int gID = lane >> 2, tig = lane & 3;
    const int j0 = jblk * 4;
    const int rb = t & 1, wb = rb ^ 1;
    const float* __restrict__ hbuf = g_h0[rb];

    float ga[2][4], cold[2], hold[2];
    int sl[2], bb_[2], jj_[2];
#pragma unroll
    for (int i = 0; i < 2; ++i) {
        int cc = lane + i * 32;
        int b_ = wm * 16 + (cc & 15);
        int j  = j0 + (cc >> 4);
        bb_[i] = b_; jj_[i] = j;
        size_t base = ((size_t)b_ * Tq + t) * Gq;
#pragma unroll
        for (int g = 0; g < 4; ++g) ga[i][g] = __ldg(&g_xw0[base + g * Hq + j]);
        cold[i] = g_c0[b_ * Hq + j];
        hold[i] = hbuf[b_ * Hq + j];
        sl[i]   = __ldg(&seq_len[b_]);
    }

    float* wbase = dynsm + wm * 4 * STGF;
    float acc[2][4] = {};
    warp_mma_loop(hbuf, hbuf, W0h, W0h, 1, j0, wbase, wm, lane, gID, tig, acc);

    __syncthreads();               // all warps done with pipelines
    stage_accs(dynsm, wm, gID, tig, acc);
    __syncwarp();
#pragma unroll
    for (int i = 0; i < 2; ++i) {
        int cc = lane + i * 32;
        int row = wm * 16 + (cc & 15), jl = cc >> 4;
        float gi = dynsm[row * 17 + 0 + jl] + ga[i][0];
        float gc_= dynsm[row * 17 + 4 + jl] + ga[i][1];
        float gf = dynsm[row * 17 + 8 + jl] + ga[i][2];
        float go = dynsm[row * 17 + 12 + jl] + ga[i][3];
        bool m = t < sl[i];
        int s = bb_[i] * Hq + jj_[i];
        float cn = sigf(gf) * cold[i] + sigf(gi) * tanhf(gc_);
        float hn = sigf(go) * tanhf(cn);
        g_c0[s]        = m ? cn : cold[i];
        g_h0[wb][s]    = m ? hn : hold[i];
        g_o0[t & 1][s] = m ? hn : 0.f;
    }
}

// ---- layer 1 body ----
__device__ void layer1_body(int t, int jblk, const int* __restrict__ seq_len,
                            const float* __restrict__ W1x, const float* __restrict__ W1h,
                            const float* __restrict__ b1, float* dynsm) {
    const int tid = threadIdx.x, lane = tid & 31, wm = tid >> 5;
    const int gID = lane >> 2, tig = lane & 3;
    const int j0 = jblk * 4;
    const int rb = t & 1, wb = rb ^ 1;
    const float* __restrict__ h1buf = g_h1[rb];

    float ga[2][4], cold[2], hold[2];
    int sl[2], bb_[2], jj_[2];
#pragma unroll
    for (int i = 0; i < 2; ++i) {
        int cc = lane + i * 32;
        int b_ = wm * 16 + (cc & 15);
        int j  = j0 + (cc >> 4);
        bb_[i] = b_; jj_[i] = j;
#pragma unroll
        for (int g = 0; g < 4; ++g) ga[i][g] = __ldg(&b1[g * Hq + j]);
        cold[i] = g_c1[b_ * Hq + j];
        hold[i] = h1buf[b_ * Hq + j];
        sl[i]   = __ldg(&seq_len[b_]);
    }

    float* wbase = dynsm + wm * 4 * STGF;
    float acc[2][4] = {};
    warp_mma_loop(g_o0[t & 1], h1buf, W1x, W1h, 2, j0, wbase, wm, lane, gID, tig, acc);

    __syncthreads();
    stage_accs(dynsm, wm, gID, tig, acc);
    __syncwarp();
#pragma unroll
    for (int i = 0; i < 2; ++i) {
        int cc = lane + i * 32;
        int row = wm * 16 + (cc & 15), jl = cc >> 4;
        float gi = dynsm[row * 17 + 0 + jl] + ga[i][0];
        float gc_= dynsm[row * 17 + 4 + jl] + ga[i][1];
        float gf = dynsm[row * 17 + 8 + jl] + ga[i][2];
        float go = dynsm[row * 17 + 12 + jl] + ga[i][3];
        bool m = t < sl[i];
        int s = bb_[i] * Hq + jj_[i];
        float cn = sigf(gf) * cold[i] + sigf(gi) * tanhf(gc_);
        float hn = sigf(go) * tanhf(cn);
        g_c1[s]     = m ? cn : cold[i];
        g_h1[wb][s] = m ? hn : hold[i];
        g_out[((size_t)bb_[i] * Tq + t) * Hq + jj_[i]] = m ? hn : 0.f;
    }
}

__global__ void __launch_bounds__(256) lstm_l0_only(const int* __restrict__ seq_len,
                                                    const float* __restrict__ W0h, int t) {
    extern __shared__ float dynsm[];
    layer0_body(t, blockIdx.x, seq_len, W0h, dynsm);
}

__global__ void __launch_bounds__(256) lstm_l1_only(const int* __restrict__ seq_len,
                                                    const float* __restrict__ W1x,
                                                    const float* __restrict__ W1h,
                                                    const float* __restrict__ b1, int t) {
    extern __shared__ float dynsm[];
    layer1_body(t, blockIdx.x, seq_len, W1x, W1h, b1, dynsm);
}

// fused: blocks 0-127 -> layer1(t);  128-255 -> layer0(t+1)
__global__ void __launch_bounds__(256) lstm_fused(const int* __restrict__ seq_len,
                                                  const float* __restrict__ W0h,
                                                  const float* __restrict__ W1x,
                                                  const float* __restrict__ W1h,
                                                  const float* __restrict__ b1, int t) {
    extern __shared__ float dynsm[];
    if (blockIdx.x < 128)
        layer1_body(t, blockIdx.x, seq_len, W1x, W1h, b1, dynsm);
    else
        layer0_body(t + 1, blockIdx.x - 128, seq_len, W0h, dynsm);
}

// ---------------- partial softmax merge; xent ----------------
__global__ void k_xent_reduce() {
    const int row  = blockIdx.x * 8 + (threadIdx.x >> 5);
    const int lane = threadIdx.x & 31;
    float m = -1e30f, s = 0.f;
    for (int p = lane; p < NBLK; p += 32) {
        float m2 = g_pm[(size_t)row * NBLK + p];
        float s2 = g_ps[(size_t)row * NBLK + p];
        float M = fmaxf(m, m2);
        s = s * expf(m - M) + s2 * expf(m2 - M);
        m = M;
    }
#pragma unroll
    for (int o = 16; o > 0; o >>= 1) {
        float m2 = __shfl_xor_sync(0xffffffff, m, o);
        float s2 = __shfl_xor_sync(0xffffffff, s, o);
        float M = fmaxf(m, m2);
        s = s * expf(m - M) + s2 * expf(m2 - M);
        m = M;
    }
    if (lane == 0) g_xent[row] = -(g_zl[row] - m - logf(s));
}

// ---------------- final masked reduction ----------------
__global__ void k_loss(const float* __restrict__ seq_mask, float* __restrict__ out) {
    const int t = threadIdx.x;
    float sx = 0.f, sw_ = 0.f;
    for (int b = 0; b < Bq; ++b) {
        int i = b * Tq + t;
        float w = seq_mask[i];
        sx  += g_xent[i] * w;
        sw_ += w;
    }
    __shared__ float sh[64];
    sh[t] = sx / (sw_ + 1e-12f);
    __syncthreads();
    for (int o = 32; o > 0; o >>= 1) { if (t < o) sh[t] += sh[t + o]; __syncthreads(); }
    if (t == 0) out[0] = sh[0] / Tq;
}

// ---------------- launch ----------------
extern "C" void kernel_launch(void* const* d_in, const int* in_sizes, int n_in,
                              void* d_out, int out_size) {
    const int*   features = (const int*)  d_in[0];
    const int*   labels   = (const int*)  d_in[1];
    const int*   seq_len  = (const int*)  d_in[2];
    const float* seq_mask = (const float*)d_in[3];
    const float* emb      = (const float*)d_in[4];
    const float* W0x      = (const float*)d_in[5];
    const float* W0h      = (const float*)d_in[6];
    const float* b0       = (const float*)d_in[7];
    const float* W1x      = (const float*)d_in[8];
    const float* W1h      = (const float*)d_in[9];
    const float* b1       = (const float*)d_in[10];
    const float* smw      = (const float*)d_in[11];
    const float* smb      = (const float*)d_in[12];
    float* out = (float*)d_out;

    cudaFuncSetAttribute(lstm_l0_only,
                         cudaFuncAttributeMaxDynamicSharedMemorySize, STEP_SMEM);
    cudaFuncSetAttribute(lstm_l1_only,
                         cudaFuncAttributeMaxDynamicSharedMemorySize, STEP_SMEM);
    cudaFuncSetAttribute(lstm_fused,
                         cudaFuncAttributeMaxDynamicSharedMemorySize, STEP_SMEM);

    k_init<<<(Bq * Hq + 255) / 256, 256>>>();

    k_xw0_tf32<<<dim3(Gq / 128, BTq / 128), 256>>>(emb, features, W0x, b0);

    // software-pipelined recurrence: L0(0); { L1(t) || L0(t+1) } x63; L1(63)
    lstm_l0_only<<<128, 256, STEP_SMEM>>>(seq_len, W0h, 0);
    for (int t = 0; t < Tq - 1; ++t)
        lstm_fused<<<256, 256, STEP_SMEM>>>(seq_len, W0h, W1x, W1h, b1, t);
    lstm_l1_only<<<128, 256, STEP_SMEM>>>(seq_len, W1x, W1h, b1, Tq - 1);

    k_logits_tf32<<<dim3(NBLK, BTq / 128), 256>>>(smw, smb, labels);
    k_xent_reduce<<<BTq / 8, 256>>>();
    k_loss<<<1, 64>>>(seq_mask, out);
}

// round 14
// speedup vs baseline: 1.4464x; 1.4464x over previous
#include <cuda_runtime.h>
#include <cuda_bf16.h>
#include <cstddef>
#include <cstdint>

#define Bq   128
#define Tq   64
#define Hq   512
#define Vq   10000
#define Gq   2048            // 4*H
#define BTq  (Bq*Tq)         // 8192
#define NBLK 79              // ceil(V/128)

// ---------------- scratch ----------------
__device__ float g_xw0[(size_t)BTq * Gq];
__device__ float g_out[(size_t)BTq * Hq];
__device__ float g_pm[(size_t)BTq * NBLK];
__device__ float g_ps[(size_t)BTq * NBLK];
__device__ float g_zl[BTq];
__device__ float g_xent[BTq];
__device__ float g_h0[2][Bq * Hq];
__device__ float g_h1[2][Bq * Hq];
__device__ float g_c0[Bq * Hq];
__device__ float g_c1[Bq * Hq];
__device__ float g_o0[2][Bq * Hq];    // double-buffered by t parity

__device__ __forceinline__ float sigf(float x) { return 1.f / (1.f + expf(-x)); }

__device__ __forceinline__ uint32_t s2u(const void* p) {
    return (uint32_t)__cvta_generic_to_shared(p);
}
__device__ __forceinline__ void cpa16(uint32_t dst, const void* src) {
    asm volatile("cp.async.cg.shared.global [%0], [%1], 16;" :: "r"(dst), "l"(src));
}
__device__ __forceinline__ void cpa16p(uint32_t dst, const void* src, bool pred) {
    int sz = pred ? 16 : 0;
    asm volatile("cp.async.cg.shared.global [%0], [%1], 16, %2;" :: "r"(dst), "l"(src), "r"(sz));
}
#define CP_COMMIT asm volatile("cp.async.commit_group;")
#define CP_WAIT1  asm volatile("cp.async.wait_group 1;")
#define CP_WAIT2  asm volatile("cp.async.wait_group 2;")

__device__ __forceinline__ void mma_tf32(float& d0, float& d1, float& d2, float& d3,
                                         unsigned a0, unsigned a1, unsigned a2, unsigned a3,
                                         unsigned b0, unsigned b1) {
    asm volatile(
        "mma.sync.aligned.m16n8k8.row.col.f32.tf32.tf32.f32 "
        "{%0,%1,%2,%3}, {%4,%5,%6,%7}, {%8,%9}, {%0,%1,%2,%3};"
        : "+f"(d0), "+f"(d1), "+f"(d2), "+f"(d3)
        : "r"(a0), "r"(a1), "r"(a2), "r"(a3), "r"(b0), "r"(b1));
}

// ---------------- init ----------------
__global__ void k_init() {
    int i = blockIdx.x * blockDim.x + threadIdx.x;
    if (i < Bq * Hq) {
        g_h0[0][i] = 0.f; g_c0[i] = 0.f;
        g_h1[0][i] = 0.f; g_c1[i] = 0.f;
    }
}

// =======================================================================
// big tf32 GEMMs (R10 proven): block 128x128, warp 32x64, k-chunk 16
// =======================================================================
#define ASTR 20
#define BSTR 136

__global__ void k_xw0_tf32(const float* __restrict__ emb, const int* __restrict__ feat,
                           const float* __restrict__ Bm, const float* __restrict__ bias) {
    const int N = Gq, K = Hq;
    __shared__ float As[2][128 * ASTR];
    __shared__ float Bs[2][16 * BSTR];
    const int tid = threadIdx.x;
    const int bx = blockIdx.x, by = blockIdx.y;
    const int warp = tid >> 5, lane = tid & 31;
    const int wm = warp & 3, wn = warp >> 2;
    const int gID = lane >> 2, tig = lane & 3;

    const int arow = tid >> 2;
    const int aq   = (tid & 3) * 4;
    const float* asrc0 = emb + (size_t)feat[by * 128 + arow] * K + aq;
    const float* asrc1 = emb + (size_t)feat[by * 128 + arow + 64] * K + aq;
    const int bk = tid >> 5, bq = tid & 31;
    const float* bsrc = Bm + (size_t)bk * N + bx * 128 + bq * 4;

    float acc[2][8][4];
#pragma unroll
    for (int mt = 0; mt < 2; ++mt)
#pragma unroll
        for (int nt = 0; nt < 8; ++nt)
#pragma unroll
            for (int e = 0; e < 4; ++e) acc[mt][nt][e] = 0.f;

    const int NC = K / 16;
    {
        cpa16(s2u(&As[0][arow * ASTR + aq]), asrc0);
        cpa16(s2u(&As[0][(arow + 64) * ASTR + aq]), asrc1);
        cpa16(s2u(&Bs[0][bk * BSTR + bq * 4]), bsrc);
        cpa16(s2u(&Bs[0][(bk + 8) * BSTR + bq * 4]), bsrc + (size_t)8 * N);
    }
    CP_COMMIT;
    for (int c = 0; c < NC; ++c) {
        const int cur = c & 1, nxt = cur ^ 1;
        if (c + 1 < NC) {
            int k0 = (c + 1) * 16;
            cpa16(s2u(&As[nxt][arow * ASTR + aq]), asrc0 + k0);
            cpa16(s2u(&As[nxt][(arow + 64) * ASTR + aq]), asrc1 + k0);
            cpa16(s2u(&Bs[nxt][bk * BSTR + bq * 4]), bsrc + (size_t)k0 * N);
            cpa16(s2u(&Bs[nxt][(bk + 8) * BSTR + bq * 4]), bsrc + (size_t)(k0 + 8) * N);
        }
        CP_COMMIT;
        CP_WAIT1;
        __syncthreads();
        const unsigned* Au = (const unsigned*)As[cur];
        const unsigned* Bu = (const unsigned*)Bs[cur];
#pragma unroll
        for (int ks = 0; ks < 2; ++ks) {
            unsigned a[2][4];
#pragma unroll
            for (int mt = 0; mt < 2; ++mt) {
                int mr = wm * 32 + mt * 16;
                a[mt][0] = Au[(mr + gID    ) * ASTR + ks * 8 + tig];
                a[mt][1] = Au[(mr + gID + 8) * ASTR + ks * 8 + tig];
                a[mt][2] = Au[(mr + gID    ) * ASTR + ks * 8 + tig + 4];
                a[mt][3] = Au[(mr + gID + 8) * ASTR + ks * 8 + tig + 4];
            }
#pragma unroll
            for (int nt = 0; nt < 8; ++nt) {
                int nc = wn * 64 + nt * 8 + gID;
                unsigned b0 = Bu[(ks * 8 + tig    ) * BSTR + nc];
                unsigned b1 = Bu[(ks * 8 + tig + 4) * BSTR + nc];
#pragma unroll
                for (int mt = 0; mt < 2; ++mt)
                    mma_tf32(acc[mt][nt][0], acc[mt][nt][1], acc[mt][nt][2], acc[mt][nt][3],
                             a[mt][0], a[mt][1], a[mt][2], a[mt][3], b0, b1);
            }
        }
        __syncthreads();
    }
#pragma unroll
    for (int mt = 0; mt < 2; ++mt) {
#pragma unroll
        for (int er = 0; er < 2; ++er) {
            int gm = by * 128 + wm * 32 + mt * 16 + gID + er * 8;
            float* crow = g_xw0 + (size_t)gm * N;
#pragma unroll
            for (int nt = 0; nt < 8; ++nt) {
                int gn = bx * 128 + wn * 64 + nt * 8 + tig * 2;
                float2 v = {acc[mt][nt][er * 2 + 0] + bias[gn],
                            acc[mt][nt][er * 2 + 1] + bias[gn + 1]};
                *(float2*)(crow + gn) = v;
            }
        }
    }
}

__global__ void k_logits_tf32(const float* __restrict__ Bm,
                              const float* __restrict__ bias,
                              const int* __restrict__ labels) {
    const int N = Vq, K = Hq;
    __shared__ float As[2][128 * ASTR];
    __shared__ float Bs[2][16 * BSTR];
    __shared__ float pm[128][9];
    __shared__ float ps[128][9];
    const int tid = threadIdx.x;
    const int bx = blockIdx.x, by = blockIdx.y;
    const int warp = tid >> 5, lane = tid & 31;
    const int wm = warp & 3, wn = warp >> 2;
    const int gID = lane >> 2, tig = lane & 3;

    const int arow = tid >> 2;
    const int aq   = (tid & 3) * 4;
    const float* asrc0 = g_out + (size_t)(by * 128 + arow) * K + aq;
    const float* asrc1 = asrc0 + (size_t)64 * K;
    const int bk = tid >> 5, bq = tid & 31;
    const int gnq = bx * 128 + bq * 4;
    const bool bpred = (gnq + 3 < N);
    const float* bsrc = Bm + (size_t)bk * N + (bpred ? gnq : 0);

    float acc[2][8][4];
#pragma unroll
    for (int mt = 0; mt < 2; ++mt)
#pragma unroll
        for (int nt = 0; nt < 8; ++nt)
#pragma unroll
            for (int e = 0; e < 4; ++e) acc[mt][nt][e] = 0.f;

    const int NC = K / 16;
    {
        cpa16(s2u(&As[0][arow * ASTR + aq]), asrc0);
        cpa16(s2u(&As[0][(arow + 64) * ASTR + aq]), asrc1);
        cpa16p(s2u(&Bs[0][bk * BSTR + bq * 4]), bsrc, bpred);
        cpa16p(s2u(&Bs[0][(bk + 8) * BSTR + bq * 4]), bsrc + (size_t)8 * N, bpred);
    }
    CP_COMMIT;
    for (int c = 0; c < NC; ++c) {
        const int cur = c & 1, nxt = cur ^ 1;
        if (c + 1 < NC) {
            int k0 = (c + 1) * 16;
            cpa16(s2u(&As[nxt][arow * ASTR + aq]), asrc0 + k0);
            cpa16(s2u(&As[nxt][(arow + 64) * ASTR + aq]), asrc1 + k0);
            cpa16p(s2u(&Bs[nxt][bk * BSTR + bq * 4]), bsrc + (size_t)k0 * N, bpred);
            cpa16p(s2u(&Bs[nxt][(bk + 8) * BSTR + bq * 4]), bsrc + (size_t)(k0 + 8) * N, bpred);
        }
        CP_COMMIT;
        CP_WAIT1;
        __syncthreads();
        const unsigned* Au = (const unsigned*)As[cur];
        const unsigned* Bu = (const unsigned*)Bs[cur];
#pragma unroll
        for (int ks = 0; ks < 2; ++ks) {
            unsigned a[2][4];
#pragma unroll
            for (int mt = 0; mt < 2; ++mt) {
                int mr = wm * 32 + mt * 16;
                a[mt][0] = Au[(mr + gID    ) * ASTR + ks * 8 + tig];
                a[mt][1] = Au[(mr + gID + 8) * ASTR + ks * 8 + tig];
                a[mt][2] = Au[(mr + gID    ) * ASTR + ks * 8 + tig + 4];
                a[mt][3] = Au[(mr + gID + 8) * ASTR + ks * 8 + tig + 4];
            }
#pragma unroll
            for (int nt = 0; nt < 8; ++nt) {
                int nc = wn * 64 + nt * 8 + gID;
                unsigned b0 = Bu[(ks * 8 + tig    ) * BSTR + nc];
                unsigned b1 = Bu[(ks * 8 + tig + 4) * BSTR + nc];
#pragma unroll
                for (int mt = 0; mt < 2; ++mt)
                    mma_tf32(acc[mt][nt][0], acc[mt][nt][1], acc[mt][nt][2], acc[mt][nt][3],
                             a[mt][0], a[mt][1], a[mt][2], a[mt][3], b0, b1);
            }
        }
        __syncthreads();
    }

#pragma unroll
    for (int mt = 0; mt < 2; ++mt) {
#pragma unroll
        for (int er = 0; er < 2; ++er) {
            int lr = wm * 32 + mt * 16 + gID + er * 8;
            int gm = by * 128 + lr;
            int lab = labels[gm];
            float lm = -1e30f, lsum = 0.f;
            float v[16];
#pragma unroll
            for (int nt = 0; nt < 8; ++nt) {
#pragma unroll
                for (int e = 0; e < 2; ++e) {
                    int gn = bx * 128 + wn * 64 + nt * 8 + tig * 2 + e;
                    float cc = acc[mt][nt][er * 2 + e];
                    if (gn < N) {
                        float z = cc + bias[gn];
                        v[nt * 2 + e] = z;
                        if (gn == lab) g_zl[gm] = z;
                        lm = fmaxf(lm, z);
                    } else v[nt * 2 + e] = -1e30f;
                }
            }
#pragma unroll
            for (int q = 0; q < 16; ++q) lsum += expf(v[q] - lm);
            if (lm <= -1e30f) lsum = 0.f;
            pm[lr][wn * 4 + tig] = lm;
            ps[lr][wn * 4 + tig] = lsum;
        }
    }
    __syncthreads();
    if (tid < 128) {
        float m = -1e30f, s = 0.f;
#pragma unroll
        for (int x = 0; x < 8; ++x) {
            float m2 = pm[tid][x], s2 = ps[tid][x];
            float M = fmaxf(m, m2);
            s = s * expf(m - M) + s2 * expf(m2 - M);
            m = M;
        }
        int gm = by * 128 + tid;
        g_pm[(size_t)gm * NBLK + bx] = m;
        g_ps[(size_t)gm * NBLK + bx] = s;
    }
}

// =======================================================================
// tf32 LSTM steps: R10 block-shared 4-stage pipeline + fragment register
// double-buffering; ONE __syncthreads per chunk.  SMEM 46 KB static.
// =======================================================================
#define SA  20
#define SB  24
#define NSTG 4

__device__ __forceinline__ void step_mma_loop(
        const float* __restrict__ A0, const float* __restrict__ A1,
        const float* __restrict__ W0, const float* __restrict__ W1,
        int nphase, int j0, float* AsmBase, float* BsmBase,
        int tid, int wm, int gID, int tig, float acc[2][4]) {
    const int ar = tid >> 1, aq = (tid & 1) * 8;
    const int bk = tid >> 2, bg = tid & 3;          // tid<64 fills B
    const int NC = nphase * 32;
    const int arow = wm * 16 + gID;

    auto issue = [&](int cc) {
        const float* Ap = (cc < 32) ? A0 : A1;
        const float* Wp = (cc < 32) ? W0 : W1;
        int k0 = (cc & 31) * 16;
        float* Ab = AsmBase + (cc & (NSTG - 1)) * (128 * SA);
        float* Bb = BsmBase + (cc & (NSTG - 1)) * (16 * SB);
        cpa16(s2u(&Ab[ar * SA + aq]),     Ap + (size_t)ar * Hq + k0 + aq);
        cpa16(s2u(&Ab[ar * SA + aq + 4]), Ap + (size_t)ar * Hq + k0 + aq + 4);
        if (tid < 64)
            cpa16(s2u(&Bb[bk * SB + bg * 4]),
                  Wp + (size_t)(k0 + bk) * Gq + bg * Hq + j0);
    };
    auto ldfr = [&](int cc, unsigned fa[2][4], unsigned fb[2][2][2]) {
        const unsigned* Au = (const unsigned*)(AsmBase + (cc & (NSTG - 1)) * (128 * SA));
        const unsigned* Bu = (const unsigned*)(BsmBase + (cc & (NSTG - 1)) * (16 * SB));
#pragma unroll
        for (int ks = 0; ks < 2; ++ks) {
            fa[ks][0] = Au[(arow    ) * SA + ks * 8 + tig];
            fa[ks][1] = Au[(arow + 8) * SA + ks * 8 + tig];
            fa[ks][2] = Au[(arow    ) * SA + ks * 8 + tig + 4];
            fa[ks][3] = Au[(arow + 8) * SA + ks * 8 + tig + 4];
#pragma unroll
            for (int nt = 0; nt < 2; ++nt) {
                int n = nt * 8 + gID;
                fb[ks][nt][0] = Bu[(ks * 8 + tig    ) * SB + n];
                fb[ks][nt][1] = Bu[(ks * 8 + tig + 4) * SB + n];
            }
        }
    };
    auto domma = [&](unsigned fa[2][4], unsigned fb[2][2][2]) {
#pragma unroll
        for (int ks = 0; ks < 2; ++ks)
#pragma unroll
            for (int nt = 0; nt < 2; ++nt)
                mma_tf32(acc[nt][0], acc[nt][1], acc[nt][2], acc[nt][3],
                         fa[ks][0], fa[ks][1], fa[ks][2], fa[ks][3],
                         fb[ks][nt][0], fb[ks][nt][1]);
    };

    // prologue: stages 0..2 in flight; frags(0) preloaded
    issue(0); CP_COMMIT;
    issue(1); CP_COMMIT;
    issue(2); CP_COMMIT;
    CP_WAIT2;                      // chunk 0 resident
    __syncthreads();
    unsigned faA[2][4], fbA[2][2][2], faB[2][4], fbB[2][2][2];
    ldfr(0, faA, fbA);

    for (int c = 0; c < NC; c += 2) {
        // even: compute c (frags A), prefetch frags(c+1) -> B
        if (c + 3 < NC) issue(c + 3);
        CP_COMMIT;                 // groups committed: c+4 -> completed >= c+2 after wait
        CP_WAIT2;                  // chunk c+1 resident
        __syncthreads();
        if (c + 1 < NC) ldfr(c + 1, faB, fbB);
        domma(faA, fbA);
        // odd: compute c+1 (frags B), prefetch frags(c+2) -> A
        if (c + 4 < NC) issue(c + 4);
        CP_COMMIT;
        CP_WAIT2;                  // chunk c+2 resident
        __syncthreads();
        if (c + 2 < NC) ldfr(c + 2, faA, fbA);
        domma(faB, fbB);
    }
}

__device__ __forceinline__ void stage_accs(float* stg, int wm, int gID, int tig,
                                           float acc[2][4]) {
#pragma unroll
    for (int nt = 0; nt < 2; ++nt)
#pragma unroll
        for (int er = 0; er < 2; ++er)
#pragma unroll
            for (int e = 0; e < 2; ++e)
                stg[(wm * 16 + gID + er * 8) * 17 + nt * 8 + tig * 2 + e] =
                    acc[nt][er * 2 + e];
}

// ---- layer 0 body: gates = h0 @ W0h + xw0[t]; writes h0[wb], o0[t&1], c0 ----
__device__ void layer0_body(int t, int jblk, const int* __restrict__ seq_len,
                            const float* __restrict__ W0h,
                            float* Asm, float* Bsm) {
    const int tid = threadIdx.x, lane = tid & 31, wm = tid >> 5;
    const int gID = lane >> 2, tig = lane & 3;
    const int j0 = jblk * 4;
    const int rb = t & 1, wb = rb ^ 1;
    const float* __restrict__ hbuf = g_h0[rb];

    float ga[2][4], cold[2], hold[2];
    int sl[2], bb_[2], jj_[2];
#pragma unroll
    for (int i = 0; i < 2; ++i) {
        int cc = lane + i * 32;
        int b_ = wm * 16 + (cc & 15);
        int j  = j0 + (cc >> 4);
        bb_[i] = b_; jj_[i] = j;
        size_t base = ((size_t)b_ * Tq + t) * Gq;
#pragma unroll
        for (int g = 0; g < 4; ++g) ga[i][g] = __ldg(&g_xw0[base + g * Hq + j]);
        cold[i] = g_c0[b_ * Hq + j];
        hold[i] = hbuf[b_ * Hq + j];
        sl[i]   = __ldg(&seq_len[b_]);
    }

    float acc[2][4] = {};
    step_mma_loop(hbuf, hbuf, W0h, W0h, 1, j0, Asm, Bsm, tid, wm, gID, tig, acc);

    __syncthreads();
    stage_accs(Asm, wm, gID, tig, acc);
    __syncwarp();
#pragma unroll
    for (int i = 0; i < 2; ++i) {
        int cc = lane + i * 32;
        int row = wm * 16 + (cc & 15), jl = cc >> 4;
        float gi = Asm[row * 17 + 0 + jl] + ga[i][0];
        float gc_= Asm[row * 17 + 4 + jl] + ga[i][1];
        float gf = Asm[row * 17 + 8 + jl] + ga[i][2];
        float go = Asm[row * 17 + 12 + jl] + ga[i][3];
        bool m = t < sl[i];
        int s = bb_[i] * Hq + jj_[i];
        float cn = sigf(gf) * cold[i] + sigf(gi) * tanhf(gc_);
        float hn = sigf(go) * tanhf(cn);
        g_c0[s]        = m ? cn : cold[i];
        g_h0[wb][s]    = m ? hn : hold[i];
        g_o0[t & 1][s] = m ? hn : 0.f;
    }
}

// ---- layer 1 body: gates = o0[t&1] @ W1x + h1 @ W1h + b1 ----
__device__ void layer1_body(int t, int jblk, const int* __restrict__ seq_len,
                            const float* __restrict__ W1x, const float* __restrict__ W1h,
                            const float* __restrict__ b1,
                            float* Asm, float* Bsm) {
    const int tid = threadIdx.x, lane = tid & 31, wm = tid >> 5;
    const int gID = lane >> 2, tig = lane & 3;
    const int j0 = jblk * 4;
    const int rb = t & 1, wb = rb ^ 1;
    const float* __restrict__ h1buf = g_h1[rb];

    float ga[2][4], cold[2], hold[2];
    int sl[2], bb_[2], jj_[2];
#pragma unroll
    for (int i = 0; i < 2; ++i) {
        int cc = lane + i * 32;
        int b_ = wm * 16 + (cc & 15);
        int j  = j0 + (cc >> 4);
        bb_[i] = b_; jj_[i] = j;
#pragma unroll
        for (int g = 0; g < 4; ++g) ga[i][g] = __ldg(&b1[g * Hq + j]);
        cold[i] = g_c1[b_ * Hq + j];
        hold[i] = h1buf[b_ * Hq + j];
        sl[i]   = __ldg(&seq_len[b_]);
    }

    float acc[2][4] = {};
    step_mma_loop(g_o0[t & 1], h1buf, W1x, W1h, 2, j0, Asm, Bsm, tid, wm, gID, tig, acc);

    __syncthreads();
    stage_accs(Asm, wm, gID, tig, acc);
    __syncwarp();
#pragma unroll
    for (int i = 0; i < 2; ++i) {
        int cc = lane + i * 32;
        int row = wm * 16 + (cc & 15), jl = cc >> 4;
        float gi = Asm[row * 17 + 0 + jl] + ga[i][0];
        float gc_= Asm[row * 17 + 4 + jl] + ga[i][1];
        float gf = Asm[row * 17 + 8 + jl] + ga[i][2];
        float go = Asm[row * 17 + 12 + jl] + ga[i][3];
        bool m = t < sl[i];
        int s = bb_[i] * Hq + jj_[i];
        float cn = sigf(gf) * cold[i] + sigf(gi) * tanhf(gc_);
        float hn = sigf(go) * tanhf(cn);
        g_c1[s]     = m ? cn : cold[i];
        g_h1[wb][s] = m ? hn : hold[i];
        g_out[((size_t)bb_[i] * Tq + t) * Hq + jj_[i]] = m ? hn : 0.f;
    }
}

__global__ void __launch_bounds__(256) lstm_l0_only(const int* __restrict__ seq_len,
                                                    const float* __restrict__ W0h, int t) {
    __shared__ float Asm[NSTG][128 * SA];
    __shared__ float Bsm[NSTG][16 * SB];
    layer0_body(t, blockIdx.x, seq_len, W0h, &Asm[0][0], &Bsm[0][0]);
}

__global__ void __launch_bounds__(256) lstm_l1_only(const int* __restrict__ seq_len,
                                                    const float* __restrict__ W1x,
                                                    const float* __restrict__ W1h,
                                                    const float* __restrict__ b1, int t) {
    __shared__ float Asm[NSTG][128 * SA];
    __shared__ float Bsm[NSTG][16 * SB];
    layer1_body(t, blockIdx.x, seq_len, W1x, W1h, b1, &Asm[0][0], &Bsm[0][0]);
}

// fused: blocks 0-127 -> layer1(t);  128-255 -> layer0(t+1)
__global__ void __launch_bounds__(256) lstm_fused(const int* __restrict__ seq_len,
                                                  const float* __restrict__ W0h,
                                                  const float* __restrict__ W1x,
                                                  const float* __restrict__ W1h,
                                                  const float* __restrict__ b1, int t) {
    __shared__ float Asm[NSTG][128 * SA];
    __shared__ float Bsm[NSTG][16 * SB];
    if (blockIdx.x < 128)
        layer1_body(t, blockIdx.x, seq_len, W1x, W1h, b1, &Asm[0][0], &Bsm[0][0]);
    else
        layer0_body(t + 1, blockIdx.x - 128, seq_len, W0h, &Asm[0][0], &Bsm[0][0]);
}

// ---------------- partial softmax merge; xent ----------------
__global__ void k_xent_reduce() {
    const int row  = blockIdx.x * 8 + (threadIdx.x >> 5);
    const int lane = threadIdx.x & 31;
    float m = -1e30f, s = 0.f;
    for (int p = lane; p < NBLK; p += 32) {
        float m2 = g_pm[(size_t)row * NBLK + p];
        float s2 = g_ps[(size_t)row * NBLK + p];
        float M = fmaxf(m, m2);
        s = s * expf(m - M) + s2 * expf(m2 - M);
        m = M;
    }
#pragma unroll
    for (int o = 16; o > 0; o >>= 1) {
        float m2 = __shfl_xor_sync(0xffffffff, m, o);
        float s2 = __shfl_xor_sync(0xffffffff, s, o);
        float M = fmaxf(m, m2);
        s = s * expf(m - M) + s2 * expf(m2 - M);
        m = M;
    }
    if (lane == 0) g_xent[row] = -(g_zl[row] - m - logf(s));
}

// ---------------- final masked reduction ----------------
__global__ void k_loss(const float* __restrict__ seq_mask, float* __restrict__ out) {
    const int t = threadIdx.x;
    float sx = 0.f, sw_ = 0.f;
    for (int b = 0; b < Bq; ++b) {
        int i = b * Tq + t;
        float w = seq_mask[i];
        sx  += g_xent[i] * w;
        sw_ += w;
    }
    __shared__ float sh[64];
    sh[t] = sx / (sw_ + 1e-12f);
    __syncthreads();
    for (int o = 32; o > 0; o >>= 1) { if (t < o) sh[t] += sh[t + o]; __syncthreads(); }
    if (t == 0) out[0] = sh[0] / Tq;
}

// ---------------- launch ----------------
extern "C" void kernel_launch(void* const* d_in, const int* in_sizes, int n_in,
                              void* d_out, int out_size) {
    const int*   features = (const int*)  d_in[0];
    const int*   labels   = (const int*)  d_in[1];
    const int*   seq_len  = (const int*)  d_in[2];
    const float* seq_mask = (const float*)d_in[3];
    const float* emb      = (const float*)d_in[4];
    const float* W0x      = (const float*)d_in[5];
    const float* W0h      = (const float*)d_in[6];
    const float* b0       = (const float*)d_in[7];
    const float* W1x      = (const float*)d_in[8];
    const float* W1h      = (const float*)d_in[9];
    const float* b1       = (const float*)d_in[10];
    const float* smw      = (const float*)d_in[11];
    const float* smb      = (const float*)d_in[12];
    float* out = (float*)d_out;

    k_init<<<(Bq * Hq + 255) / 256, 256>>>();

    k_xw0_tf32<<<dim3(Gq / 128, BTq / 128), 256>>>(emb, features, W0x, b0);

    // software-pipelined recurrence: L0(0); { L1(t) || L0(t+1) } x63; L1(63)
    lstm_l0_only<<<128, 256>>>(seq_len, W0h, 0);
    for (int t = 0; t < Tq - 1; ++t)
        lstm_fused<<<256, 256>>>(seq_len, W0h, W1x, W1h, b1, t);
    lstm_l1_only<<<128, 256>>>(seq_len, W1x, W1h, b1, Tq - 1);

    k_logits_tf32<<<dim3(NBLK, BTq / 128), 256>>>(smw, smb, labels);
    k_xent_reduce<<<BTq / 8, 256>>>();
    k_loss<<<1, 64>>>(seq_mask, out);
}

// round 15
// speedup vs baseline: 1.6287x; 1.1260x over previous
#include <cuda_runtime.h>
#include <cuda_bf16.h>
#include <cstddef>
#include <cstdint>

#define Bq   128
#define Tq   64
#define Hq   512
#define Vq   10000
#define Gq   2048            // 4*H
#define BTq  (Bq*Tq)         // 8192
#define NBLK 79              // ceil(V/128)
#define KS0  2               // layer0 K-splits (K=512 -> 256)
#define KS1  4               // layer1 K-splits (K=1024 -> 256)
#define NJB  16              // j-blocks (32 j each)

// ---------------- scratch ----------------
__device__ float g_xw0[(size_t)BTq * Gq];      // row-major [bt][gatecol]
__device__ float g_out[(size_t)BTq * Hq];
__device__ float g_pm[(size_t)BTq * NBLK];
__device__ float g_ps[(size_t)BTq * NBLK];
__device__ float g_zl[BTq];
__device__ float g_xent[BTq];
__device__ float g_h0[2][Bq * Hq];
__device__ float g_h1[2][Bq * Hq];
__device__ float g_c0[Bq * Hq];
__device__ float g_c1[Bq * Hq];
__device__ float g_o0[2][Bq * Hq];             // dbl-buffered by t parity
// gate partials: [split][jblk][row 128][col 128] (col = g*32 + jl)
__device__ float g_q0[KS0][NJB][128 * 128];
__device__ float g_q1[KS1][NJB][128 * 128];
__device__ unsigned g_cnt0[NJB];
__device__ unsigned g_cnt1[NJB];

__device__ __forceinline__ float sigf(float x) { return 1.f / (1.f + expf(-x)); }

__device__ __forceinline__ uint32_t s2u(const void* p) {
    return (uint32_t)__cvta_generic_to_shared(p);
}
__device__ __forceinline__ void cpa16(uint32_t dst, const void* src) {
    asm volatile("cp.async.cg.shared.global [%0], [%1], 16;" :: "r"(dst), "l"(src));
}
__device__ __forceinline__ void cpa16p(uint32_t dst, const void* src, bool pred) {
    int sz = pred ? 16 : 0;
    asm volatile("cp.async.cg.shared.global [%0], [%1], 16, %2;" :: "r"(dst), "l"(src), "r"(sz));
}
#define CP_COMMIT asm volatile("cp.async.commit_group;")
#define CP_WAIT1  asm volatile("cp.async.wait_group 1;")

__device__ __forceinline__ void mma_tf32(float& d0, float& d1, float& d2, float& d3,
                                         unsigned a0, unsigned a1, unsigned a2, unsigned a3,
                                         unsigned b0, unsigned b1) {
    asm volatile(
        "mma.sync.aligned.m16n8k8.row.col.f32.tf32.tf32.f32 "
        "{%0,%1,%2,%3}, {%4,%5,%6,%7}, {%8,%9}, {%0,%1,%2,%3};"
        : "+f"(d0), "+f"(d1), "+f"(d2), "+f"(d3)
        : "r"(a0), "r"(a1), "r"(a2), "r"(a3), "r"(b0), "r"(b1));
}

// ---------------- init ----------------
__global__ void k_init() {
    int i = blockIdx.x * blockDim.x + threadIdx.x;
    if (i < Bq * Hq) {
        g_h0[0][i] = 0.f; g_c0[i] = 0.f;
        g_h1[0][i] = 0.f; g_c1[i] = 0.f;
    }
    if (i < NJB) { g_cnt0[i] = 0u; g_cnt1[i] = 0u; }
}

// =======================================================================
// big tf32 GEMMs (R10 proven): block 128x128, warp 32x64, k-chunk 16
// =======================================================================
#define ASTR 20
#define BSTR 136

__global__ void k_xw0_tf32(const float* __restrict__ emb, const int* __restrict__ feat,
                           const float* __restrict__ Bm, const float* __restrict__ bias) {
    const int N = Gq, K = Hq;
    __shared__ float As[2][128 * ASTR];
    __shared__ float Bs[2][16 * BSTR];
    const int tid = threadIdx.x;
    const int bx = blockIdx.x, by = blockIdx.y;
    const int warp = tid >> 5, lane = tid & 31;
    const int wm = warp & 3, wn = warp >> 2;
    const int gID = lane >> 2, tig = lane & 3;

    const int arow = tid >> 2;
    const int aq   = (tid & 3) * 4;
    const float* asrc0 = emb + (size_t)feat[by * 128 + arow] * K + aq;
    const float* asrc1 = emb + (size_t)feat[by * 128 + arow + 64] * K + aq;
    const int bk = tid >> 5, bq = tid & 31;
    const float* bsrc = Bm + (size_t)bk * N + bx * 128 + bq * 4;

    float acc[2][8][4];
#pragma unroll
    for (int mt = 0; mt < 2; ++mt)
#pragma unroll
        for (int nt = 0; nt < 8; ++nt)
#pragma unroll
            for (int e = 0; e < 4; ++e) acc[mt][nt][e] = 0.f;

    const int NC = K / 16;
    {
        cpa16(s2u(&As[0][arow * ASTR + aq]), asrc0);
        cpa16(s2u(&As[0][(arow + 64) * ASTR + aq]), asrc1);
        cpa16(s2u(&Bs[0][bk * BSTR + bq * 4]), bsrc);
        cpa16(s2u(&Bs[0][(bk + 8) * BSTR + bq * 4]), bsrc + (size_t)8 * N);
    }
    CP_COMMIT;
    for (int c = 0; c < NC; ++c) {
        const int cur = c & 1, nxt = cur ^ 1;
        if (c + 1 < NC) {
            int k0 = (c + 1) * 16;
            cpa16(s2u(&As[nxt][arow * ASTR + aq]), asrc0 + k0);
            cpa16(s2u(&As[nxt][(arow + 64) * ASTR + aq]), asrc1 + k0);
            cpa16(s2u(&Bs[nxt][bk * BSTR + bq * 4]), bsrc + (size_t)k0 * N);
            cpa16(s2u(&Bs[nxt][(bk + 8) * BSTR + bq * 4]), bsrc + (size_t)(k0 + 8) * N);
        }
        CP_COMMIT;
        CP_WAIT1;
        __syncthreads();
        const unsigned* Au = (const unsigned*)As[cur];
        const unsigned* Bu = (const unsigned*)Bs[cur];
#pragma unroll
        for (int ks = 0; ks < 2; ++ks) {
            unsigned a[2][4];
#pragma unroll
            for (int mt = 0; mt < 2; ++mt) {
                int mr = wm * 32 + mt * 16;
                a[mt][0] = Au[(mr + gID    ) * ASTR + ks * 8 + tig];
                a[mt][1] = Au[(mr + gID + 8) * ASTR + ks * 8 + tig];
                a[mt][2] = Au[(mr + gID    ) * ASTR + ks * 8 + tig + 4];
                a[mt][3] = Au[(mr + gID + 8) * ASTR + ks * 8 + tig + 4];
            }
#pragma unroll
            for (int nt = 0; nt < 8; ++nt) {
                int nc = wn * 64 + nt * 8 + gID;
                unsigned b0 = Bu[(ks * 8 + tig    ) * BSTR + nc];
                unsigned b1 = Bu[(ks * 8 + tig + 4) * BSTR + nc];
#pragma unroll
                for (int mt = 0; mt < 2; ++mt)
                    mma_tf32(acc[mt][nt][0], acc[mt][nt][1], acc[mt][nt][2], acc[mt][nt][3],
                             a[mt][0], a[mt][1], a[mt][2], a[mt][3], b0, b1);
            }
        }
        __syncthreads();
    }
#pragma unroll
    for (int mt = 0; mt < 2; ++mt) {
#pragma unroll
        for (int er = 0; er < 2; ++er) {
            int gm = by * 128 + wm * 32 + mt * 16 + gID + er * 8;
            float* crow = g_xw0 + (size_t)gm * N;
#pragma unroll
            for (int nt = 0; nt < 8; ++nt) {
                int gn = bx * 128 + wn * 64 + nt * 8 + tig * 2;
                float2 v = {acc[mt][nt][er * 2 + 0] + bias[gn],
                            acc[mt][nt][er * 2 + 1] + bias[gn + 1]};
                *(float2*)(crow + gn) = v;
            }
        }
    }
}

__global__ void k_logits_tf32(const float* __restrict__ Bm,
                              const float* __restrict__ bias,
                              const int* __restrict__ labels) {
    const int N = Vq, K = Hq;
    __shared__ float As[2][128 * ASTR];
    __shared__ float Bs[2][16 * BSTR];
    __shared__ float pm[128][9];
    __shared__ float ps[128][9];
    const int tid = threadIdx.x;
    const int bx = blockIdx.x, by = blockIdx.y;
    const int warp = tid >> 5, lane = tid & 31;
    const int wm = warp & 3, wn = warp >> 2;
    const int gID = lane >> 2, tig = lane & 3;

    const int arow = tid >> 2;
    const int aq   = (tid & 3) * 4;
    const float* asrc0 = g_out + (size_t)(by * 128 + arow) * K + aq;
    const float* asrc1 = asrc0 + (size_t)64 * K;
    const int bk = tid >> 5, bq = tid & 31;
    const int gnq = bx * 128 + bq * 4;
    const bool bpred = (gnq + 3 < N);
    const float* bsrc = Bm + (size_t)bk * N + (bpred ? gnq : 0);

    float acc[2][8][4];
#pragma unroll
    for (int mt = 0; mt < 2; ++mt)
#pragma unroll
        for (int nt = 0; nt < 8; ++nt)
#pragma unroll
            for (int e = 0; e < 4; ++e) acc[mt][nt][e] = 0.f;

    const int NC = K / 16;
    {
        cpa16(s2u(&As[0][arow * ASTR + aq]), asrc0);
        cpa16(s2u(&As[0][(arow + 64) * ASTR + aq]), asrc1);
        cpa16p(s2u(&Bs[0][bk * BSTR + bq * 4]), bsrc, bpred);
        cpa16p(s2u(&Bs[0][(bk + 8) * BSTR + bq * 4]), bsrc + (size_t)8 * N, bpred);
    }
    CP_COMMIT;
    for (int c = 0; c < NC; ++c) {
        const int cur = c & 1, nxt = cur ^ 1;
        if (c + 1 < NC) {
            int k0 = (c + 1) * 16;
            cpa16(s2u(&As[nxt][arow * ASTR + aq]), asrc0 + k0);
            cpa16(s2u(&As[nxt][(arow + 64) * ASTR + aq]), asrc1 + k0);
            cpa16p(s2u(&Bs[nxt][bk * BSTR + bq * 4]), bsrc + (size_t)k0 * N, bpred);
            cpa16p(s2u(&Bs[nxt][(bk + 8) * BSTR + bq * 4]), bsrc + (size_t)(k0 + 8) * N, bpred);
        }
        CP_COMMIT;
        CP_WAIT1;
        __syncthreads();
        const unsigned* Au = (const unsigned*)As[cur];
        const unsigned* Bu = (const unsigned*)Bs[cur];
#pragma unroll
        for (int ks = 0; ks < 2; ++ks) {
            unsigned a[2][4];
#pragma unroll
            for (int mt = 0; mt < 2; ++mt) {
                int mr = wm * 32 + mt * 16;
                a[mt][0] = Au[(mr + gID    ) * ASTR + ks * 8 + tig];
                a[mt][1] = Au[(mr + gID + 8) * ASTR + ks * 8 + tig];
                a[mt][2] = Au[(mr + gID    ) * ASTR + ks * 8 + tig + 4];
                a[mt][3] = Au[(mr + gID + 8) * ASTR + ks * 8 + tig + 4];
            }
#pragma unroll
            for (int nt = 0; nt < 8; ++nt) {
                int nc = wn * 64 + nt * 8 + gID;
                unsigned b0 = Bu[(ks * 8 + tig    ) * BSTR + nc];
                unsigned b1 = Bu[(ks * 8 + tig + 4) * BSTR + nc];
#pragma unroll
                for (int mt = 0; mt < 2; ++mt)
                    mma_tf32(acc[mt][nt][0], acc[mt][nt][1], acc[mt][nt][2], acc[mt][nt][3],
                             a[mt][0], a[mt][1], a[mt][2], a[mt][3], b0, b1);
            }
        }
        __syncthreads();
    }

#pragma unroll
    for (int mt = 0; mt < 2; ++mt) {
#pragma unroll
        for (int er = 0; er < 2; ++er) {
            int lr = wm * 32 + mt * 16 + gID + er * 8;
            int gm = by * 128 + lr;
            int lab = labels[gm];
            float lm = -1e30f, lsum = 0.f;
            float v[16];
#pragma unroll
            for (int nt = 0; nt < 8; ++nt) {
#pragma unroll
                for (int e = 0; e < 2; ++e) {
                    int gn = bx * 128 + wn * 64 + nt * 8 + tig * 2 + e;
                    float cc = acc[mt][nt][er * 2 + e];
                    if (gn < N) {
                        float z = cc + bias[gn];
                        v[nt * 2 + e] = z;
                        if (gn == lab) g_zl[gm] = z;
                        lm = fmaxf(lm, z);
                    } else v[nt * 2 + e] = -1e30f;
                }
            }
#pragma unroll
            for (int q = 0; q < 16; ++q) lsum += expf(v[q] - lm);
            if (lm <= -1e30f) lsum = 0.f;
            pm[lr][wn * 4 + tig] = lm;
            ps[lr][wn * 4 + tig] = lsum;
        }
    }
    __syncthreads();
    if (tid < 128) {
        float m = -1e30f, s = 0.f;
#pragma unroll
        for (int x = 0; x < 8; ++x) {
            float m2 = pm[tid][x], s2 = ps[tid][x];
            float M = fmaxf(m, m2);
            s = s * expf(m - M) + s2 * expf(m2 - M);
            m = M;
        }
        int gm = by * 128 + tid;
        g_pm[(size_t)gm * NBLK + bx] = m;
        g_ps[(size_t)gm * NBLK + bx] = s;
    }
}

// =======================================================================
// LSTM steps: 128x128 tiles (cols = 4 gates x 32 j interleaved), split-K.
// Each block: 16 k-chunks (k16, 2-stage pipeline), partial -> global
// [row][col]; last arriver reduces (float4) + cell update.
// Dyn SMEM 69632 B: pipeline overlays low half; acc staging uses [128][136].
// =======================================================================
#define STEP_SMEM (128 * BSTR * 4)     // 69632

// 16-chunk 128x128 GEMM into acc; cols c: g=c>>5, jl=c&31 -> W col g*512+j0+jl
__device__ __forceinline__ void gemm16(
        const float* __restrict__ A, const float* __restrict__ W,
        int kbase, int j0, float* sm,
        int tid, int wm, int wn, int gID, int tig, float acc[2][8][4]) {
    float* As0 = sm;
    float* As1 = sm + 128 * ASTR;
    float* Bs0 = sm + 2 * 128 * ASTR;
    float* Bs1 = Bs0 + 16 * BSTR;
    float* Asx[2] = {As0, As1};
    float* Bsx[2] = {Bs0, Bs1};

    const int arow = tid >> 2;                  // 0..63 (+64)
    const int aq   = (tid & 3) * 4;
    const float* as0 = A + (size_t)arow * Hq + kbase + aq;
    const float* as1 = A + (size_t)(arow + 64) * Hq + kbase + aq;

    auto bfill = [&](float* Bb, int k0) {
#pragma unroll
        for (int e = 0; e < 2; ++e) {
            int it = tid * 2 + e;                // 0..511
            int kr = it >> 5, qc = it & 31;
            int g = qc >> 3, jl4 = (qc & 7) * 4;
            cpa16(s2u(&Bb[kr * BSTR + qc * 4]),
                  W + (size_t)(kbase + k0 + kr) * Gq + g * Hq + j0 + jl4);
        }
    };

    {
        cpa16(s2u(&As0[arow * ASTR + aq]), as0);
        cpa16(s2u(&As0[(arow + 64) * ASTR + aq]), as1);
        bfill(Bs0, 0);
    }
    CP_COMMIT;
    for (int c = 0; c < 16; ++c) {
        const int cur = c & 1, nxt = cur ^ 1;
        if (c + 1 < 16) {
            int k0 = (c + 1) * 16;
            cpa16(s2u(&Asx[nxt][arow * ASTR + aq]), as0 + k0);
            cpa16(s2u(&Asx[nxt][(arow + 64) * ASTR + aq]), as1 + k0);
            bfill(Bsx[nxt], k0);
        }
        CP_COMMIT;
        CP_WAIT1;
        __syncthreads();
        const unsigned* Au = (const unsigned*)Asx[cur];
        const unsigned* Bu = (const unsigned*)Bsx[cur];
#pragma unroll
        for (int ks = 0; ks < 2; ++ks) {
            unsigned a[2][4];
#pragma unroll
            for (int mt = 0; mt < 2; ++mt) {
                int mr = wm * 32 + mt * 16;
                a[mt][0] = Au[(mr + gID    ) * ASTR + ks * 8 + tig];
                a[mt][1] = Au[(mr + gID + 8) * ASTR + ks * 8 + tig];
                a[mt][2] = Au[(mr + gID    ) * ASTR + ks * 8 + tig + 4];
                a[mt][3] = Au[(mr + gID + 8) * ASTR + ks * 8 + tig + 4];
            }
#pragma unroll
            for (int nt = 0; nt < 8; ++nt) {
                int nc = wn * 64 + nt * 8 + gID;
                unsigned b0 = Bu[(ks * 8 + tig    ) * BSTR + nc];
                unsigned b1 = Bu[(ks * 8 + tig + 4) * BSTR + nc];
#pragma unroll
                for (int mt = 0; mt < 2; ++mt)
                    mma_tf32(acc[mt][nt][0], acc[mt][nt][1], acc[mt][nt][2], acc[mt][nt][3],
                             a[mt][0], a[mt][1], a[mt][2], a[mt][3], b0, b1);
            }
        }
        __syncthreads();
    }
}

// stage accs into sm[128][136] then write partial [row][col] (coalesced)
__device__ __forceinline__ void dump_partial(float* sm, float* part,
                                             int tid, int wm, int wn, int gID, int tig,
                                             float acc[2][8][4]) {
    __syncthreads();   // pipeline smem no longer needed
#pragma unroll
    for (int mt = 0; mt < 2; ++mt)
#pragma unroll
        for (int er = 0; er < 2; ++er) {
            int row = wm * 32 + mt * 16 + gID + er * 8;
#pragma unroll
            for (int nt = 0; nt < 8; ++nt) {
                int col = wn * 64 + nt * 8 + tig * 2;
                sm[row * BSTR + col]     = acc[mt][nt][er * 2 + 0];
                sm[row * BSTR + col + 1] = acc[mt][nt][er * 2 + 1];
            }
        }
    __syncthreads();
    int row = tid >> 1, hf = (tid & 1) * 64;
#pragma unroll
    for (int q = 0; q < 16; ++q) {
        *(float4*)&part[row * 128 + hf + q * 4] =
            *(const float4*)&sm[row * BSTR + hf + q * 4];
    }
}

__device__ __forceinline__ bool arrive_last(unsigned* cnt, int ks, int tid, int* flag) {
    __threadfence();
    __syncthreads();
    if (tid == 0) {
        unsigned old = atomicAdd(cnt, 1u);
        *flag = (old == (unsigned)(ks - 1));
        if (*flag) *cnt = 0u;
    }
    __syncthreads();
    bool w = (*flag != 0);
    if (w) __threadfence();
    return w;
}

// ---- layer 0 split block ----
__device__ void layer0_split(int t, int jblk, int split,
                             const int* __restrict__ seq_len,
                             const float* __restrict__ W0h,
                             float* sm, int* flag) {
    const int tid = threadIdx.x, lane = tid & 31;
    const int warp = tid >> 5, wm = warp & 3, wn = warp >> 2;
    const int gID = lane >> 2, tig = lane & 3;
    const int j0 = jblk * 32;
    const int rb = t & 1, wb = rb ^ 1;
    const float* __restrict__ hbuf = g_h0[rb];

    float acc[2][8][4];
#pragma unroll
    for (int mt = 0; mt < 2; ++mt)
#pragma unroll
        for (int nt = 0; nt < 8; ++nt)
#pragma unroll
            for (int e = 0; e < 4; ++e) acc[mt][nt][e] = 0.f;

    gemm16(hbuf, W0h, split * 256, j0, sm, tid, wm, wn, gID, tig, acc);
    dump_partial(sm, g_q0[split][jblk], tid, wm, wn, gID, tig, acc);

    if (!arrive_last(&g_cnt0[jblk], KS0, tid, flag)) return;

    // reducer + cell update: thread = (rowq = tid>>3)*4 rows x (jq = tid&7)*4 j
    const int rowq = tid >> 3, jq = tid & 7;
#pragma unroll
    for (int rr = 0; rr < 4; ++rr) {
        int row = rowq * 4 + rr;
        bool m = t < seq_len[row];
        int j = j0 + jq * 4;
        size_t xb = ((size_t)row * Tq + t) * Gq;
        float4 gv[4];
#pragma unroll
        for (int g = 0; g < 4; ++g) {
            float4 v = *(const float4*)&g_xw0[xb + g * Hq + j];
#pragma unroll
            for (int s = 0; s < KS0; ++s) {
                float4 p = *(const float4*)&g_q0[s][jblk][row * 128 + g * 32 + jq * 4];
                v.x += p.x; v.y += p.y; v.z += p.z; v.w += p.w;
            }
            gv[g] = v;
        }
        int si = row * Hq + j;
        float4 cold = *(const float4*)&g_c0[si];
        float4 hold = *(const float4*)&hbuf[si];
        float4 cn_, hn_, on_;
        {
            const float* gi = (const float*)&gv[0];
            const float* gc = (const float*)&gv[1];
            const float* gf = (const float*)&gv[2];
            const float* go = (const float*)&gv[3];
            float* cp = (float*)&cn_;
            float* hp = (float*)&hn_;
            float* op = (float*)&on_;
            const float* co = (const float*)&cold;
            const float* ho = (const float*)&hold;
#pragma unroll
            for (int e = 0; e < 4; ++e) {
                float cn = sigf(gf[e]) * co[e] + sigf(gi[e]) * tanhf(gc[e]);
                float hn = sigf(go[e]) * tanhf(cn);
                cp[e] = m ? cn : co[e];
                hp[e] = m ? hn : ho[e];
                op[e] = m ? hn : 0.f;
            }
        }
        *(float4*)&g_c0[si]        = cn_;
        *(float4*)&g_h0[wb][si]    = hn_;
        *(float4*)&g_o0[t & 1][si] = on_;
    }
}

// ---- layer 1 split block: splits 0,1 -> o0 @ W1x halves; 2,3 -> h1 @ W1h ----
__device__ void layer1_split(int t, int jblk, int split,
                             const int* __restrict__ seq_len,
                             const float* __restrict__ W1x,
                             const float* __restrict__ W1h,
                             const float* __restrict__ b1,
                             float* sm, int* flag) {
    const int tid = threadIdx.x, lane = tid & 31;
    const int warp = tid >> 5, wm = warp & 3, wn = warp >> 2;
    const int gID = lane >> 2, tig = lane & 3;
    const int j0 = jblk * 32;
    const int rb = t & 1, wb = rb ^ 1;
    const float* __restrict__ h1buf = g_h1[rb];

    const float* A = (split < 2) ? g_o0[t & 1] : h1buf;
    const float* W = (split < 2) ? W1x : W1h;
    int kbase = (split & 1) * 256;

    float acc[2][8][4];
#pragma unroll
    for (int mt = 0; mt < 2; ++mt)
#pragma unroll
        for (int nt = 0; nt < 8; ++nt)
#pragma unroll
            for (int e = 0; e < 4; ++e) acc[mt][nt][e] = 0.f;

    gemm16(A, W, kbase, j0, sm, tid, wm, wn, gID, tig, acc);
    dump_partial(sm, g_q1[split][jblk], tid, wm, wn, gID, tig, acc);

    if (!arrive_last(&g_cnt1[jblk], KS1, tid, flag)) return;

    const int rowq = tid >> 3, jq = tid & 7;
#pragma unroll
    for (int rr = 0; rr < 4; ++rr) {
        int row = rowq * 4 + rr;
        bool m = t < seq_len[row];
        int j = j0 + jq * 4;
        float4 gv[4];
#pragma unroll
        for (int g = 0; g < 4; ++g) {
            float4 v = *(const float4*)&b1[g * Hq + j];
#pragma unroll
            for (int s = 0; s < KS1; ++s) {
                float4 p = *(const float4*)&g_q1[s][jblk][row * 128 + g * 32 + jq * 4];
                v.x += p.x; v.y += p.y; v.z += p.z; v.w += p.w;
            }
            gv[g] = v;
        }
        int si = row * Hq + j;
        float4 cold = *(const float4*)&g_c1[si];
        float4 hold = *(const float4*)&h1buf[si];
        float4 cn_, hn_, on_;
        {
            const float* gi = (const float*)&gv[0];
            const float* gc = (const float*)&gv[1];
            const float* gf = (const float*)&gv[2];
            const float* go = (const float*)&gv[3];
            float* cp = (float*)&cn_;
            float* hp = (float*)&hn_;
            float* op = (float*)&on_;
            const float* co = (const float*)&cold;
            const float* ho = (const float*)&hold;
#pragma unroll
            for (int e = 0; e < 4; ++e) {
                float cn = sigf(gf[e]) * co[e] + sigf(gi[e]) * tanhf(gc[e]);
                float hn = sigf(go[e]) * tanhf(cn);
                cp[e] = m ? cn : co[e];
                hp[e] = m ? hn : ho[e];
                op[e] = m ? hn : 0.f;
            }
        }
        *(float4*)&g_c1[si]     = cn_;
        *(float4*)&g_h1[wb][si] = hn_;
        *(float4*)&g_out[((size_t)row * Tq + t) * Hq + j] = on_;
    }
}

__global__ void __launch_bounds__(256) lstm_l0_only(const int* __restrict__ seq_len,
                                                    const float* __restrict__ W0h, int t) {
    extern __shared__ float sm[];
    __shared__ int flag;
    layer0_split(t, blockIdx.x >> 1, blockIdx.x & 1, seq_len, W0h, sm, &flag);
}

__global__ void __launch_bounds__(256) lstm_l1_only(const int* __restrict__ seq_len,
                                                    const float* __restrict__ W1x,
                                                    const float* __restrict__ W1h,
                                                    const float* __restrict__ b1, int t) {
    extern __shared__ float sm[];
    __shared__ int flag;
    layer1_split(t, blockIdx.x >> 2, blockIdx.x & 3, seq_len, W1x, W1h, b1, sm, &flag);
}

// fused: blocks 0-63 -> layer1(t) splits;  64-95 -> layer0(t+1) splits
__global__ void __launch_bounds__(256) lstm_fused(const int* __restrict__ seq_len,
                                                  const float* __restrict__ W0h,
                                                  const float* __restrict__ W1x,
                                                  const float* __restrict__ W1h,
                                                  const float* __restrict__ b1, int t) {
    extern __shared__ float sm[];
    __shared__ int flag;
    if (blockIdx.x < 64)
        layer1_split(t, blockIdx.x >> 2, blockIdx.x & 3, seq_len, W1x, W1h, b1, sm, &flag);
    else {
        int idx = blockIdx.x - 64;
        layer0_split(t + 1, idx >> 1, idx & 1, seq_len, W0h, sm, &flag);
    }
}

// ---------------- partial softmax merge; xent ----------------
__global__ void k_xent_reduce() {
    const int row  = blockIdx.x * 8 + (threadIdx.x >> 5);
    const int lane = threadIdx.x & 31;
    float m = -1e30f, s = 0.f;
    for (int p = lane; p < NBLK; p += 32) {
        float m2 = g_pm[(size_t)row * NBLK + p];
        float s2 = g_ps[(size_t)row * NBLK + p];
        float M = fmaxf(m, m2);
        s = s * expf(m - M) + s2 * expf(m2 - M);
        m = M;
    }
#pragma unroll
    for (int o = 16; o > 0; o >>= 1) {
        float m2 = __shfl_xor_sync(0xffffffff, m, o);
        float s2 = __shfl_xor_sync(0xffffffff, s, o);
        float M = fmaxf(m, m2);
        s = s * expf(m - M) + s2 * expf(m2 - M);
        m = M;
    }
    if (lane == 0) g_xent[row] = -(g_zl[row] - m - logf(s));
}

// ---------------- final masked reduction ----------------
__global__ void k_loss(const float* __restrict__ seq_mask, float* __restrict__ out) {
    const int t = threadIdx.x;
    float sx = 0.f, sw_ = 0.f;
    for (int b = 0; b < Bq; ++b) {
        int i = b * Tq + t;
        float w = seq_mask[i];
        sx  += g_xent[i] * w;
        sw_ += w;
    }
    __shared__ float sh[64];
    sh[t] = sx / (sw_ + 1e-12f);
    __syncthreads();
    for (int o = 32; o > 0; o >>= 1) { if (t < o) sh[t] += sh[t + o]; __syncthreads(); }
    if (t == 0) out[0] = sh[0] / Tq;
}

// ---------------- launch ----------------
extern "C" void kernel_launch(void* const* d_in, const int* in_sizes, int n_in,
                              void* d_out, int out_size) {
    const int*   features = (const int*)  d_in[0];
    const int*   labels   = (const int*)  d_in[1];
    const int*   seq_len  = (const int*)  d_in[2];
    const float* seq_mask = (const float*)d_in[3];
    const float* emb      = (const float*)d_in[4];
    const float* W0x      = (const float*)d_in[5];
    const float* W0h      = (const float*)d_in[6];
    const float* b0       = (const float*)d_in[7];
    const float* W1x      = (const float*)d_in[8];
    const float* W1h      = (const float*)d_in[9];
    const float* b1       = (const float*)d_in[10];
    const float* smw      = (const float*)d_in[11];
    const float* smb      = (const float*)d_in[12];
    float* out = (float*)d_out;

    cudaFuncSetAttribute(lstm_l0_only,
                         cudaFuncAttributeMaxDynamicSharedMemorySize, STEP_SMEM);
    cudaFuncSetAttribute(lstm_l1_only,
                         cudaFuncAttributeMaxDynamicSharedMemorySize, STEP_SMEM);
    cudaFuncSetAttribute(lstm_fused,
                         cudaFuncAttributeMaxDynamicSharedMemorySize, STEP_SMEM);

    k_init<<<(Bq * Hq + 255) / 256, 256>>>();

    k_xw0_tf32<<<dim3(Gq / 128, BTq / 128), 256>>>(emb, features, W0x, b0);

    // split-K software-pipelined recurrence
    lstm_l0_only<<<NJB * KS0, 256, STEP_SMEM>>>(seq_len, W0h, 0);
    for (int t = 0; t < Tq - 1; ++t)
        lstm_fused<<<NJB * (KS0 + KS1), 256, STEP_SMEM>>>(seq_len, W0h, W1x, W1h, b1, t);
    lstm_l1_only<<<NJB * KS1, 256, STEP_SMEM>>>(seq_len, W1x, W1h, b1, Tq - 1);

    k_logits_tf32<<<dim3(NBLK, BTq / 128), 256>>>(smw, smb, labels);
    k_xent_reduce<<<BTq / 8, 256>>>();
    k_loss<<<1, 64>>>(seq_mask, out);
}